// round 16
// baseline (speedup 1.0000x reference)
#include <cuda_runtime.h>
#include <cuda_fp16.h>
#include <cstdint>

#define BB 8
#define CC 512
#define TT 1024
#define NHD 8
#define HD 64
#define MM (BB*TT)

// ---------------- scratch (device globals; no allocs allowed) ---------------
__device__ __half g_kvh[MM*CC];
__device__ __half g_qh [MM*CC];
__device__ __half g_KO [MM*CC];
__device__ __half g_QO [MM*CC];
__device__ __half g_VO [MM*CC];
__device__ __half g_Yh [MM*CC];
__device__ __half g_Wt[4*CC*CC];

// ---------------- helpers ---------------------------------------------------
__device__ __forceinline__ uint32_t smem_u32(const void* p) {
    uint32_t a;
    asm("{ .reg .u64 t; cvta.to.shared.u64 t, %1; cvt.u32.u64 %0, t; }" : "=r"(a) : "l"(p));
    return a;
}
__device__ __forceinline__ void cpa16(uint32_t d, const void* s) {
    asm volatile("cp.async.cg.shared.global [%0], [%1], 16;" :: "r"(d), "l"(s));
}
__device__ __forceinline__ void cp_commit() {
    asm volatile("cp.async.commit_group;" ::: "memory");
}
template<int N> __device__ __forceinline__ void cp_wait() {
    asm volatile("cp.async.wait_group %0;" :: "n"(N) : "memory");
}
__device__ __forceinline__ void ldx4(uint32_t* r, uint32_t addr) {
    asm volatile("ldmatrix.sync.aligned.m8n8.x4.shared.b16 {%0,%1,%2,%3}, [%4];"
        : "=r"(r[0]), "=r"(r[1]), "=r"(r[2]), "=r"(r[3]) : "r"(addr));
}
__device__ __forceinline__ void ldx4t(uint32_t* r, uint32_t addr) {
    asm volatile("ldmatrix.sync.aligned.m8n8.x4.trans.shared.b16 {%0,%1,%2,%3}, [%4];"
        : "=r"(r[0]), "=r"(r[1]), "=r"(r[2]), "=r"(r[3]) : "r"(addr));
}
__device__ __forceinline__ void mma16816h(float* c, const uint32_t* a, uint32_t b0, uint32_t b1) {
    asm volatile("mma.sync.aligned.m16n8k16.row.col.f32.f16.f16.f32 "
        "{%0,%1,%2,%3}, {%4,%5,%6,%7}, {%8,%9}, {%0,%1,%2,%3};"
        : "+f"(c[0]), "+f"(c[1]), "+f"(c[2]), "+f"(c[3])
        : "r"(a[0]), "r"(a[1]), "r"(a[2]), "r"(a[3]), "r"(b0), "r"(b1));
}
__device__ __forceinline__ uint32_t pack_h2(float lo, float hi) {
    uint32_t d;
    asm("cvt.rn.f16x2.f32 %0, %1, %2;" : "=r"(d) : "f"(hi), "f"(lo));
    return d;
}
__device__ __forceinline__ uint32_t h2exp2(uint32_t x) {
    uint32_t d;
    asm("ex2.approx.f16x2 %0, %1;" : "=r"(d) : "r"(x));
    return d;
}
#define ONE2 0x3C003C00u   // f16x2 {1.0, 1.0}

// ------- LayerNorm (both inputs in one launch): [B,C,T] -> fp16 [B*T,C] ------
__global__ __launch_bounds__(256) void ln2_kernel(
    const float* __restrict__ in0, const float* __restrict__ in1,
    const float* __restrict__ w0, const float* __restrict__ b0v,
    const float* __restrict__ w1, const float* __restrict__ b1v,
    __half* __restrict__ H0, __half* __restrict__ H1)
{
    int z = blockIdx.z;
    const float* in = z ? in1 : in0;
    const float* w  = z ? w1  : w0;
    const float* bs = z ? b1v : b0v;
    __half* H = z ? H1 : H0;

    __shared__ float tile[8][CC + 4];
    int b = blockIdx.y;
    int t0 = blockIdx.x * 8;
    int tid = threadIdx.x;
    const float* src = in + (size_t)b*CC*TT + t0;
#pragma unroll
    for (int it = 0; it < 8; it++) {
        int v = it*256 + tid;
        int c = v >> 2, jp = v & 3;
        float2 f = *(const float2*)(src + (size_t)c*TT + jp*2);
        tile[jp*2+0][c] = f.x;
        tile[jp*2+1][c] = f.y;
    }
    __syncthreads();
    int wid = tid >> 5, lane = tid & 31;
    float x[16], s = 0.f, s2 = 0.f;
#pragma unroll
    for (int i = 0; i < 16; i++) {
        x[i] = tile[wid][lane + i*32];
        s += x[i]; s2 = fmaf(x[i], x[i], s2);
    }
#pragma unroll
    for (int o = 16; o; o >>= 1) {
        s  += __shfl_xor_sync(0xffffffffu, s,  o);
        s2 += __shfl_xor_sync(0xffffffffu, s2, o);
    }
    float mu = s * (1.f/CC);
    float var = s2 * (1.f/CC) - mu*mu;
    float rinv = rsqrtf(var + 1e-5f);
    size_t base = (size_t)(b*TT + t0 + wid)*CC;
#pragma unroll
    for (int i = 0; i < 16; i++) {
        int c = lane + i*32;
        float y = (x[i]-mu)*rinv*w[c] + bs[c];
        H[base + c] = __float2half_rn(y);
    }
}

// ------------- W prep: transpose [K,N]->[N,K], single fp16 -------------------
__global__ __launch_bounds__(256) void wprep_kernel(
    const float* __restrict__ W0, const float* __restrict__ W1,
    const float* __restrict__ W2, const float* __restrict__ W3,
    __half* __restrict__ Wt)
{
    __shared__ float tile[32][33];
    int mid = blockIdx.z;
    const float* W = (mid == 0) ? W0 : (mid == 1) ? W1 : (mid == 2) ? W2 : W3;
    __half* Ww = Wt + (size_t)mid*CC*CC;
    int k0 = blockIdx.x*32, n0 = blockIdx.y*32;
    int tx = threadIdx.x & 31, ty = threadIdx.x >> 5;
    for (int i = ty; i < 32; i += 8)
        tile[i][tx] = W[(size_t)(k0+i)*CC + n0 + tx];
    __syncthreads();
    for (int i = ty; i < 32; i += 8)
        Ww[(size_t)(n0+i)*CC + k0 + tx] = __float2half_rn(tile[tx][i]);
}

// ------------- fp16 HMMA GEMM: 8 warps 32x64, KC=64, ring-3 ------------------
// Fragment sets double-buffered across ks: ks+1 LDSM issue before ks MMAs.
#define TILE64 16384u          // 128 rows x 128 B
#define STG64 (2u*TILE64)      // 32768 per stage (A | B)
#define DSMG (3*32768)         // 98304 ring

#define GEMM_LDFRAG(buf, dbv, ksv) do { \
    uint32_t sw_ = (uint32_t)((((ksv)*2 + lg) ^ lsw7) << 4); \
    uint32_t aad_ = (dbv) + (uint32_t)(wm + lrow)*128 + sw_; \
    ldx4(ahp[buf][0], aad_); \
    ldx4(ahp[buf][1], aad_ + 16*128); \
    _Pragma("unroll") for (int nf2_ = 0; nf2_ < 4; nf2_++) \
        ldx4(bhp[buf][nf2_], (dbv) + TILE64 + (uint32_t)(wn + nf2_*16 + lrow)*128 + sw_); \
} while (0)

#define GEMM_MAIN(AhP, BwP) \
    extern __shared__ __align__(128) char smg[]; \
    uint32_t sbase = smem_u32(smg); \
    int tid = threadIdx.x; \
    int wid = tid >> 5, lane = tid & 31; \
    int n0 = blockIdx.x * 128, m0 = blockIdx.y * 128; \
    int wm = (wid & 3) * 32, wn = (wid >> 2) * 64; \
    int r = tid >> 1; \
    int c4 = (tid & 1) * 4; \
    float acc[2][8][4]; \
    _Pragma("unroll") for (int i = 0; i < 2; i++) \
    _Pragma("unroll") for (int j = 0; j < 8; j++) \
    _Pragma("unroll") for (int qq = 0; qq < 4; qq++) acc[i][j][qq] = 0.f; \
    auto stage = [&](int s) { \
        uint32_t db = sbase + (uint32_t)(s % 3) * STG64; \
        size_t aoff = (size_t)(m0 + r)*CC + s*64; \
        size_t boff = (size_t)(n0 + r)*CC + s*64; \
        uint32_t dr = db + (uint32_t)r*128; \
        _Pragma("unroll") for (int j = 0; j < 4; j++) { \
            int c = c4 + j; \
            uint32_t sw = (uint32_t)((c ^ (r & 7)) << 4); \
            cpa16(dr + sw,          AhP + aoff + c*8); \
            cpa16(dr + sw + TILE64, BwP + boff + c*8); \
        } \
    }; \
    stage(0); cp_commit(); \
    stage(1); cp_commit(); \
    int lrow = lane & 15, lg = lane >> 4; \
    uint32_t lsw7 = (uint32_t)(lrow & 7); \
    uint32_t ahp[2][2][4], bhp[2][4][4]; \
    for (int s = 0; s < 8; s++) { \
        if (s < 7) cp_wait<1>(); else cp_wait<0>(); \
        __syncthreads(); \
        if (s + 2 < 8) { stage(s + 2); cp_commit(); } \
        uint32_t db = sbase + (uint32_t)(s % 3) * STG64; \
        GEMM_LDFRAG(0, db, 0); \
        _Pragma("unroll") for (int ks = 0; ks < 4; ks++) { \
            int cur = ks & 1; \
            if (ks < 3) GEMM_LDFRAG(cur ^ 1, db, ks + 1); \
            _Pragma("unroll") for (int nf2 = 0; nf2 < 4; nf2++) \
            _Pragma("unroll") for (int mf = 0; mf < 2; mf++) { \
                mma16816h(acc[mf][nf2*2+0], ahp[cur][mf], bhp[cur][nf2][0], bhp[cur][nf2][2]); \
                mma16816h(acc[mf][nf2*2+1], ahp[cur][mf], bhp[cur][nf2][1], bhp[cur][nf2][3]); \
            } \
        } \
    }

// merged K/Q/V projections: blockIdx.z selects matrix; fp16 outputs
// Q scale folds 1/sqrt(hd) * log2(e) -> attention runs in exp2 domain.
__global__ __launch_bounds__(256, 2) void gemm_qkv(
    const __half* __restrict__ A0, const __half* __restrict__ A1,
    const __half* __restrict__ Wt,
    const float* __restrict__ bk, const float* __restrict__ bq,
    const float* __restrict__ bv,
    __half* __restrict__ KO, __half* __restrict__ QO, __half* __restrict__ VO)
{
    int z = blockIdx.z;
    const __half* Ah = (z == 1) ? A1 : A0;
    const __half* Bw = Wt + (size_t)z*CC*CC;
    const float* bias = (z == 0) ? bk : (z == 1) ? bq : bv;
    float scale = (z == 1) ? 0.18033688f : 1.0f;   // 0.125 * log2(e)
    __half* Oh = (z == 0) ? KO : (z == 1) ? QO : VO;

    GEMM_MAIN(Ah, Bw);

    int crow = lane >> 2, ccol = (lane & 3) * 2;
#pragma unroll
    for (int mf = 0; mf < 2; mf++) {
        int m = m0 + wm + mf*16 + crow;
#pragma unroll
        for (int nf = 0; nf < 8; nf++) {
            int n = n0 + wn + nf*8 + ccol;
            float b0 = bias[n], b1 = bias[n+1];
            float v0 = (acc[mf][nf][0] + b0) * scale;
            float v1 = (acc[mf][nf][1] + b1) * scale;
            float v2 = (acc[mf][nf][2] + b0) * scale;
            float v3 = (acc[mf][nf][3] + b1) * scale;
            *(uint32_t*)(Oh + (size_t)m*CC + n)     = pack_h2(v0, v1);
            *(uint32_t*)(Oh + (size_t)(m+8)*CC + n) = pack_h2(v2, v3);
        }
    }
}

// final projection fused with residual + transpose back to [B,C,T]
__global__ __launch_bounds__(256, 2) void gemm_p(
    const __half* __restrict__ Ahp2, const __half* __restrict__ Bwp,
    const float* __restrict__ bias, const float* __restrict__ kvres,
    float* __restrict__ out)
{
    GEMM_MAIN(Ahp2, Bwp);

    // stage C^T in smem (reuse ring): st[n][m], rows padded to 132 floats
    __syncthreads();
    float* st = (float*)smg;
    int crow = lane >> 2, ccol = (lane & 3) * 2;
#pragma unroll
    for (int mf = 0; mf < 2; mf++) {
        int m = wm + mf*16 + crow;
#pragma unroll
        for (int nf = 0; nf < 8; nf++) {
            int n = wn + nf*8 + ccol;
            float b0 = bias[n0+n], b1 = bias[n0+n+1];
            st[(n+0)*132 + m]     = acc[mf][nf][0] + b0;
            st[(n+1)*132 + m]     = acc[mf][nf][1] + b1;
            st[(n+0)*132 + m + 8] = acc[mf][nf][2] + b0;
            st[(n+1)*132 + m + 8] = acc[mf][nf][3] + b1;
        }
    }
    __syncthreads();
    int b = m0 >> 10, t0 = m0 & 1023;
#pragma unroll
    for (int it = 0; it < 16; it++) {
        int v = it*256 + tid;
        int n = v >> 5, mq = (v & 31) * 4;
        size_t idx = (size_t)b*CC*TT + (size_t)(n0 + n)*TT + t0 + mq;
        float4 cv = *(float4*)&st[n*132 + mq];
        float4 rv = *(const float4*)(kvres + idx);
        cv.x += rv.x; cv.y += rv.y; cv.z += rv.z; cv.w += rv.w;
        *(float4*)(out + idx) = cv;
    }
}

// --- fp16 HMMA flash attention: exp2-in-pack, no max, ones-MMA sums ----------
// QK inner loop: batch 4 K-fragment LDSM per kc ahead of the 8 MMAs.
// smem: Q 16K | 2 stages x (K 16K + V 16K) = 80K.
#define AKV 32768u

__global__ __launch_bounds__(256, 2) void attn_tc()
{
    extern __shared__ __align__(128) char sma[];
    uint32_t sb = smem_u32(sma);
    int tid = threadIdx.x, wid = tid >> 5, lane = tid & 31;
    int qt = blockIdx.x, h = blockIdx.y, b = blockIdx.z;
    int q0 = qt * 128;

    // stage Q (128 rows x 8 chunks)
#pragma unroll
    for (int i = 0; i < 4; i++) {
        int v = i*256 + tid;
        int row = v >> 3, ch = v & 7;
        uint32_t off = (uint32_t)row*128 + (uint32_t)((ch ^ (row & 7)) << 4);
        size_t src = (size_t)(b*TT + q0 + row)*CC + h*HD + ch*8;
        cpa16(sb + off, g_QO + src);
    }
    // stage 128 keys of K and V
    auto stage_kv = [&](int st) {
        uint32_t base = sb + 16384u + (uint32_t)(st & 1)*AKV;
#pragma unroll
        for (int i = 0; i < 4; i++) {
            int v = i*256 + tid;
            int row = v >> 3, ch = v & 7;
            uint32_t off = (uint32_t)row*128 + (uint32_t)((ch ^ (row & 7)) << 4);
            size_t src = (size_t)(b*TT + st*128 + row)*CC + h*HD + ch*8;
            cpa16(base + off,          g_KO + src);
            cpa16(base + 16384u + off, g_VO + src);
        }
    };
    stage_kv(0);
    cp_commit();

    int wm = wid * 16;
    int lrow = lane & 15, lg = lane >> 4;

    float s[8][4], o[8][4], lacc[4];
#pragma unroll
    for (int i = 0; i < 8; i++)
#pragma unroll
        for (int j = 0; j < 4; j++) o[i][j] = 0.f;
#pragma unroll
    for (int j = 0; j < 4; j++) lacc[j] = 0.f;
    uint32_t qf[4][4];

    for (int st = 0; st < 8; st++) {
        cp_wait<0>();
        __syncthreads();
        if (st + 1 < 8) { stage_kv(st + 1); cp_commit(); }
        if (st == 0) {
#pragma unroll
            for (int kc = 0; kc < 4; kc++) {
                int row = wm + lrow;
                uint32_t off = (uint32_t)row*128 + (uint32_t)(((kc*2 + lg) ^ (row & 7)) << 4);
                ldx4(qf[kc], sb + off);
            }
        }
        uint32_t kb0 = sb + 16384u + (uint32_t)(st & 1)*AKV;

#pragma unroll
        for (int half = 0; half < 2; half++) {
            int r0 = half * 64;

            // ---- S = Q K^T: per kc, batch 4 LDSM then 8 MMAs ----
#pragma unroll
            for (int i = 0; i < 8; i++)
#pragma unroll
                for (int j = 0; j < 4; j++) s[i][j] = 0.f;
#pragma unroll
            for (int kc = 0; kc < 4; kc++) {
                uint32_t kh[4][4];
#pragma unroll
                for (int ng = 0; ng < 4; ng++) {
                    int row = r0 + ng*16 + lrow;
                    uint32_t off = (uint32_t)row*128 + (uint32_t)(((kc*2 + lg) ^ (row & 7)) << 4);
                    ldx4(kh[ng], kb0 + off);
                }
#pragma unroll
                for (int ng = 0; ng < 4; ng++) {
                    mma16816h(s[2*ng+0], qf[kc], kh[ng][0], kh[ng][2]);
                    mma16816h(s[2*ng+1], qf[kc], kh[ng][1], kh[ng][3]);
                }
            }

            // ---- P = exp2(S) fused into f16x2 pack; O += P V; l += P @ 1 ----
#pragma unroll
            for (int kc = 0; kc < 4; kc++) {
                uint32_t pah[4];
                pah[0] = h2exp2(pack_h2(s[2*kc][0],   s[2*kc][1]));
                pah[1] = h2exp2(pack_h2(s[2*kc][2],   s[2*kc][3]));
                pah[2] = h2exp2(pack_h2(s[2*kc+1][0], s[2*kc+1][1]));
                pah[3] = h2exp2(pack_h2(s[2*kc+1][2], s[2*kc+1][3]));
                mma16816h(lacc, pah, ONE2, ONE2);
                int g = lane >> 3;
                int vrow = r0 + kc*16 + (g & 1)*8 + (lane & 7);
#pragma unroll
                for (int nf2 = 0; nf2 < 4; nf2++) {
                    int chv = nf2*2 + (g >> 1);
                    uint32_t va = kb0 + 16384u + (uint32_t)vrow*128
                                + (uint32_t)((chv ^ (vrow & 7)) << 4);
                    uint32_t vh4[4];
                    ldx4t(vh4, va);
                    mma16816h(o[2*nf2+0], pah, vh4[0], vh4[1]);
                    mma16816h(o[2*nf2+1], pah, vh4[2], vh4[3]);
                }
            }
        }
    }

    // lacc cols are all equal: lacc[0] = row sum (row r), lacc[2] = row r+8
    float ri0 = 1.f / lacc[0], ri1 = 1.f / lacc[2];
    int r = lane >> 2, c2 = (lane & 3) * 2;
#pragma unroll
    for (int nf = 0; nf < 8; nf++) {
        size_t i0 = (size_t)(b*TT + q0 + wm + r)*CC     + h*HD + nf*8 + c2;
        size_t i1 = (size_t)(b*TT + q0 + wm + r + 8)*CC + h*HD + nf*8 + c2;
        *(uint32_t*)(g_Yh + i0) = pack_h2(o[nf][0]*ri0, o[nf][1]*ri0);
        *(uint32_t*)(g_Yh + i1) = pack_h2(o[nf][2]*ri1, o[nf][3]*ri1);
    }
}

// ---------------------------------------------------------------------------
extern "C" void kernel_launch(void* const* d_in, const int* in_sizes, int n_in,
                              void* d_out, int out_size)
{
    const float* q       = (const float*)d_in[0];
    const float* kv      = (const float*)d_in[1];
    const float* ln_kv_w = (const float*)d_in[2];
    const float* ln_kv_b = (const float*)d_in[3];
    const float* ln_q_w  = (const float*)d_in[4];
    const float* ln_q_b  = (const float*)d_in[5];
    const float* Wk      = (const float*)d_in[6];
    const float* bk      = (const float*)d_in[7];
    const float* Wq      = (const float*)d_in[8];
    const float* bq      = (const float*)d_in[9];
    const float* Wv      = (const float*)d_in[10];
    const float* bv      = (const float*)d_in[11];
    const float* Wp      = (const float*)d_in[12];
    const float* bp      = (const float*)d_in[13];
    float* out = (float*)d_out;

    __half *kvh, *qh, *Yh, *Wt, *KO, *QO, *VO;
    cudaGetSymbolAddress((void**)&kvh, g_kvh);
    cudaGetSymbolAddress((void**)&qh,  g_qh);
    cudaGetSymbolAddress((void**)&Yh,  g_Yh);
    cudaGetSymbolAddress((void**)&Wt,  g_Wt);
    cudaGetSymbolAddress((void**)&KO,  g_KO);
    cudaGetSymbolAddress((void**)&QO,  g_QO);
    cudaGetSymbolAddress((void**)&VO,  g_VO);

    const int ASM_SZ = 16384 + 2*AKV;   // 81920 B
    cudaFuncSetAttribute(gemm_qkv, cudaFuncAttributeMaxDynamicSharedMemorySize, DSMG);
    cudaFuncSetAttribute(gemm_p,   cudaFuncAttributeMaxDynamicSharedMemorySize, DSMG);
    cudaFuncSetAttribute(attn_tc,  cudaFuncAttributeMaxDynamicSharedMemorySize, ASM_SZ);

    wprep_kernel<<<dim3(16,16,4), 256>>>(Wk, Wq, Wv, Wp, Wt);
    ln2_kernel<<<dim3(TT/8, BB, 2), 256>>>(kv, q, ln_kv_w, ln_kv_b,
                                           ln_q_w, ln_q_b, kvh, qh);

    gemm_qkv<<<dim3(CC/128, MM/128, 3), 256, DSMG>>>(
        kvh, qh, Wt, bk, bq, bv, KO, QO, VO);

    attn_tc<<<dim3(TT/128, NHD, BB), 256, ASM_SZ>>>();

    gemm_p<<<dim3(CC/128, MM/128), 256, DSMG>>>(Yh, Wt + 3*CC*CC, bp, kv, out);
}

// round 17
// speedup vs baseline: 1.0386x; 1.0386x over previous
#include <cuda_runtime.h>
#include <cuda_fp16.h>
#include <cstdint>

#define BB 8
#define CC 512
#define TT 1024
#define NHD 8
#define HD 64
#define MM (BB*TT)

// ---------------- scratch (device globals; no allocs allowed) ---------------
__device__ __half g_kvh[MM*CC];
__device__ __half g_qh [MM*CC];
__device__ __half g_KO [MM*CC];
__device__ __half g_QO [MM*CC];
__device__ __half g_VO [MM*CC];
__device__ __half g_Yh [MM*CC];
__device__ __half g_Wt[4*CC*CC];

// ---------------- helpers ---------------------------------------------------
__device__ __forceinline__ uint32_t smem_u32(const void* p) {
    uint32_t a;
    asm("{ .reg .u64 t; cvta.to.shared.u64 t, %1; cvt.u32.u64 %0, t; }" : "=r"(a) : "l"(p));
    return a;
}
__device__ __forceinline__ void cpa16(uint32_t d, const void* s) {
    asm volatile("cp.async.cg.shared.global [%0], [%1], 16;" :: "r"(d), "l"(s));
}
__device__ __forceinline__ void cp_commit() {
    asm volatile("cp.async.commit_group;" ::: "memory");
}
template<int N> __device__ __forceinline__ void cp_wait() {
    asm volatile("cp.async.wait_group %0;" :: "n"(N) : "memory");
}
__device__ __forceinline__ void ldx4(uint32_t* r, uint32_t addr) {
    asm volatile("ldmatrix.sync.aligned.m8n8.x4.shared.b16 {%0,%1,%2,%3}, [%4];"
        : "=r"(r[0]), "=r"(r[1]), "=r"(r[2]), "=r"(r[3]) : "r"(addr));
}
__device__ __forceinline__ void ldx4t(uint32_t* r, uint32_t addr) {
    asm volatile("ldmatrix.sync.aligned.m8n8.x4.trans.shared.b16 {%0,%1,%2,%3}, [%4];"
        : "=r"(r[0]), "=r"(r[1]), "=r"(r[2]), "=r"(r[3]) : "r"(addr));
}
__device__ __forceinline__ void mma16816h(float* c, const uint32_t* a, uint32_t b0, uint32_t b1) {
    asm volatile("mma.sync.aligned.m16n8k16.row.col.f32.f16.f16.f32 "
        "{%0,%1,%2,%3}, {%4,%5,%6,%7}, {%8,%9}, {%0,%1,%2,%3};"
        : "+f"(c[0]), "+f"(c[1]), "+f"(c[2]), "+f"(c[3])
        : "r"(a[0]), "r"(a[1]), "r"(a[2]), "r"(a[3]), "r"(b0), "r"(b1));
}
__device__ __forceinline__ uint32_t pack_h2(float lo, float hi) {
    uint32_t d;
    asm("cvt.rn.f16x2.f32 %0, %1, %2;" : "=r"(d) : "f"(hi), "f"(lo));
    return d;
}
__device__ __forceinline__ uint32_t h2exp2(uint32_t x) {
    uint32_t d;
    asm("ex2.approx.f16x2 %0, %1;" : "=r"(d) : "r"(x));
    return d;
}
#define ONE2 0x3C003C00u   // f16x2 {1.0, 1.0}

// ------- LayerNorm (both inputs in one launch): [B,C,T] -> fp16 [B*T,C] ------
__global__ __launch_bounds__(256) void ln2_kernel(
    const float* __restrict__ in0, const float* __restrict__ in1,
    const float* __restrict__ w0, const float* __restrict__ b0v,
    const float* __restrict__ w1, const float* __restrict__ b1v,
    __half* __restrict__ H0, __half* __restrict__ H1)
{
    int z = blockIdx.z;
    const float* in = z ? in1 : in0;
    const float* w  = z ? w1  : w0;
    const float* bs = z ? b1v : b0v;
    __half* H = z ? H1 : H0;

    __shared__ float tile[8][CC + 4];
    int b = blockIdx.y;
    int t0 = blockIdx.x * 8;
    int tid = threadIdx.x;
    const float* src = in + (size_t)b*CC*TT + t0;
#pragma unroll
    for (int it = 0; it < 8; it++) {
        int v = it*256 + tid;
        int c = v >> 2, jp = v & 3;
        float2 f = *(const float2*)(src + (size_t)c*TT + jp*2);
        tile[jp*2+0][c] = f.x;
        tile[jp*2+1][c] = f.y;
    }
    __syncthreads();
    int wid = tid >> 5, lane = tid & 31;
    float x[16], s = 0.f, s2 = 0.f;
#pragma unroll
    for (int i = 0; i < 16; i++) {
        x[i] = tile[wid][lane + i*32];
        s += x[i]; s2 = fmaf(x[i], x[i], s2);
    }
#pragma unroll
    for (int o = 16; o; o >>= 1) {
        s  += __shfl_xor_sync(0xffffffffu, s,  o);
        s2 += __shfl_xor_sync(0xffffffffu, s2, o);
    }
    float mu = s * (1.f/CC);
    float var = s2 * (1.f/CC) - mu*mu;
    float rinv = rsqrtf(var + 1e-5f);
    size_t base = (size_t)(b*TT + t0 + wid)*CC;
#pragma unroll
    for (int i = 0; i < 16; i++) {
        int c = lane + i*32;
        float y = (x[i]-mu)*rinv*w[c] + bs[c];
        H[base + c] = __float2half_rn(y);
    }
}

// ------------- W prep: transpose [K,N]->[N,K], single fp16 -------------------
__global__ __launch_bounds__(256) void wprep_kernel(
    const float* __restrict__ W0, const float* __restrict__ W1,
    const float* __restrict__ W2, const float* __restrict__ W3,
    __half* __restrict__ Wt)
{
    __shared__ float tile[32][33];
    int mid = blockIdx.z;
    const float* W = (mid == 0) ? W0 : (mid == 1) ? W1 : (mid == 2) ? W2 : W3;
    __half* Ww = Wt + (size_t)mid*CC*CC;
    int k0 = blockIdx.x*32, n0 = blockIdx.y*32;
    int tx = threadIdx.x & 31, ty = threadIdx.x >> 5;
    for (int i = ty; i < 32; i += 8)
        tile[i][tx] = W[(size_t)(k0+i)*CC + n0 + tx];
    __syncthreads();
    for (int i = ty; i < 32; i += 8)
        Ww[(size_t)(n0+i)*CC + k0 + tx] = __float2half_rn(tile[tx][i]);
}

// ------- fp16 HMMA GEMM: 128x64 block, 8 warps 32x32 tiles, 3 CTAs/SM --------
// KC=64 stages, ring-3. A tile 16K + B tile 8K per stage.
#define TILE_A 16384u
#define STG_G  24576u          // A 16K | B 8K
#define DSMG   (3*24576)       // 73728 ring

#define GEMM_MAIN(AhP, BwP) \
    extern __shared__ __align__(128) char smg[]; \
    uint32_t sbase = smem_u32(smg); \
    int tid = threadIdx.x; \
    int wid = tid >> 5, lane = tid & 31; \
    int n0 = blockIdx.x * 64, m0 = blockIdx.y * 128; \
    int wm = (wid & 3) * 32, wn = (wid >> 2) * 32; \
    int r = tid >> 1; \
    int c4 = (tid & 1) * 4; \
    int rb = tid >> 2; \
    int cb = (tid & 3) * 2; \
    float acc[2][4][4]; \
    _Pragma("unroll") for (int i = 0; i < 2; i++) \
    _Pragma("unroll") for (int j = 0; j < 4; j++) \
    _Pragma("unroll") for (int qq = 0; qq < 4; qq++) acc[i][j][qq] = 0.f; \
    auto stage = [&](int s) { \
        uint32_t db = sbase + (uint32_t)(s % 3) * STG_G; \
        size_t aoff = (size_t)(m0 + r)*CC + s*64; \
        uint32_t dr = db + (uint32_t)r*128; \
        _Pragma("unroll") for (int j = 0; j < 4; j++) { \
            int c = c4 + j; \
            uint32_t sw = (uint32_t)((c ^ (r & 7)) << 4); \
            cpa16(dr + sw, AhP + aoff + c*8); \
        } \
        size_t boff = (size_t)(n0 + rb)*CC + s*64; \
        uint32_t drb = db + TILE_A + (uint32_t)rb*128; \
        _Pragma("unroll") for (int j = 0; j < 2; j++) { \
            int c = cb + j; \
            uint32_t sw = (uint32_t)((c ^ (rb & 7)) << 4); \
            cpa16(drb + sw, BwP + boff + c*8); \
        } \
    }; \
    stage(0); cp_commit(); \
    stage(1); cp_commit(); \
    int lrow = lane & 15, lg = lane >> 4; \
    uint32_t lsw7 = (uint32_t)(lrow & 7); \
    for (int s = 0; s < 8; s++) { \
        if (s < 7) cp_wait<1>(); else cp_wait<0>(); \
        __syncthreads(); \
        if (s + 2 < 8) { stage(s + 2); cp_commit(); } \
        uint32_t db = sbase + (uint32_t)(s % 3) * STG_G; \
        _Pragma("unroll") for (int ks = 0; ks < 4; ks++) { \
            uint32_t sw = (uint32_t)(((ks*2 + lg) ^ lsw7) << 4); \
            uint32_t aad = db + (uint32_t)(wm + lrow)*128 + sw; \
            uint32_t ah[2][4], bh[2][4]; \
            ldx4(ah[0], aad); \
            ldx4(ah[1], aad + 16*128); \
            _Pragma("unroll") for (int nf2 = 0; nf2 < 2; nf2++) \
                ldx4(bh[nf2], db + TILE_A + (uint32_t)(wn + nf2*16 + lrow)*128 + sw); \
            _Pragma("unroll") for (int nf2 = 0; nf2 < 2; nf2++) \
            _Pragma("unroll") for (int mf = 0; mf < 2; mf++) { \
                mma16816h(acc[mf][nf2*2+0], ah[mf], bh[nf2][0], bh[nf2][2]); \
                mma16816h(acc[mf][nf2*2+1], ah[mf], bh[nf2][1], bh[nf2][3]); \
            } \
        } \
    }

// merged K/Q/V projections: blockIdx.z selects matrix; fp16 outputs
// Q scale folds 1/sqrt(hd) * log2(e) -> attention runs in exp2 domain.
__global__ __launch_bounds__(256, 3) void gemm_qkv(
    const __half* __restrict__ A0, const __half* __restrict__ A1,
    const __half* __restrict__ Wt,
    const float* __restrict__ bk, const float* __restrict__ bq,
    const float* __restrict__ bv,
    __half* __restrict__ KO, __half* __restrict__ QO, __half* __restrict__ VO)
{
    int z = blockIdx.z;
    const __half* Ah = (z == 1) ? A1 : A0;
    const __half* Bw = Wt + (size_t)z*CC*CC;
    const float* bias = (z == 0) ? bk : (z == 1) ? bq : bv;
    float scale = (z == 1) ? 0.18033688f : 1.0f;   // 0.125 * log2(e)
    __half* Oh = (z == 0) ? KO : (z == 1) ? QO : VO;

    GEMM_MAIN(Ah, Bw);

    int crow = lane >> 2, ccol = (lane & 3) * 2;
#pragma unroll
    for (int mf = 0; mf < 2; mf++) {
        int m = m0 + wm + mf*16 + crow;
#pragma unroll
        for (int nf = 0; nf < 4; nf++) {
            int n = n0 + wn + nf*8 + ccol;
            float b0 = bias[n], b1 = bias[n+1];
            float v0 = (acc[mf][nf][0] + b0) * scale;
            float v1 = (acc[mf][nf][1] + b1) * scale;
            float v2 = (acc[mf][nf][2] + b0) * scale;
            float v3 = (acc[mf][nf][3] + b1) * scale;
            *(uint32_t*)(Oh + (size_t)m*CC + n)     = pack_h2(v0, v1);
            *(uint32_t*)(Oh + (size_t)(m+8)*CC + n) = pack_h2(v2, v3);
        }
    }
}

// final projection fused with residual + transpose back to [B,C,T]
__global__ __launch_bounds__(256, 3) void gemm_p(
    const __half* __restrict__ Ahp, const __half* __restrict__ Bwp,
    const float* __restrict__ bias, const float* __restrict__ kvres,
    float* __restrict__ out)
{
    GEMM_MAIN(Ahp, Bwp);

    // stage C^T in smem (reuse ring): st[n][m], 64 x 132 floats
    __syncthreads();
    float* st = (float*)smg;
    int crow = lane >> 2, ccol = (lane & 3) * 2;
#pragma unroll
    for (int mf = 0; mf < 2; mf++) {
        int m = wm + mf*16 + crow;
#pragma unroll
        for (int nf = 0; nf < 4; nf++) {
            int n = wn + nf*8 + ccol;
            float b0 = bias[n0+n], b1 = bias[n0+n+1];
            st[(n+0)*132 + m]     = acc[mf][nf][0] + b0;
            st[(n+1)*132 + m]     = acc[mf][nf][1] + b1;
            st[(n+0)*132 + m + 8] = acc[mf][nf][2] + b0;
            st[(n+1)*132 + m + 8] = acc[mf][nf][3] + b1;
        }
    }
    __syncthreads();
    int b = m0 >> 10, t0 = m0 & 1023;
#pragma unroll
    for (int it = 0; it < 8; it++) {
        int v = it*256 + tid;
        int n = v >> 5, mq = (v & 31) * 4;
        size_t idx = (size_t)b*CC*TT + (size_t)(n0 + n)*TT + t0 + mq;
        float4 cv = *(float4*)&st[n*132 + mq];
        float4 rv = *(const float4*)(kvres + idx);
        cv.x += rv.x; cv.y += rv.y; cv.z += rv.z; cv.w += rv.w;
        *(float4*)(out + idx) = cv;
    }
}

// --- fp16 HMMA flash attention: exp2-in-pack, no max, ones-MMA sums (R15) ----
// smem: Q 16K | 2 stages x (K 16K + V 16K) = 80K.
#define AKV 32768u

__global__ __launch_bounds__(256, 2) void attn_tc()
{
    extern __shared__ __align__(128) char sma[];
    uint32_t sb = smem_u32(sma);
    int tid = threadIdx.x, wid = tid >> 5, lane = tid & 31;
    int qt = blockIdx.x, h = blockIdx.y, b = blockIdx.z;
    int q0 = qt * 128;

    // stage Q (128 rows x 8 chunks)
#pragma unroll
    for (int i = 0; i < 4; i++) {
        int v = i*256 + tid;
        int row = v >> 3, ch = v & 7;
        uint32_t off = (uint32_t)row*128 + (uint32_t)((ch ^ (row & 7)) << 4);
        size_t src = (size_t)(b*TT + q0 + row)*CC + h*HD + ch*8;
        cpa16(sb + off, g_QO + src);
    }
    // stage 128 keys of K and V
    auto stage_kv = [&](int st) {
        uint32_t base = sb + 16384u + (uint32_t)(st & 1)*AKV;
#pragma unroll
        for (int i = 0; i < 4; i++) {
            int v = i*256 + tid;
            int row = v >> 3, ch = v & 7;
            uint32_t off = (uint32_t)row*128 + (uint32_t)((ch ^ (row & 7)) << 4);
            size_t src = (size_t)(b*TT + st*128 + row)*CC + h*HD + ch*8;
            cpa16(base + off,          g_KO + src);
            cpa16(base + 16384u + off, g_VO + src);
        }
    };
    stage_kv(0);
    cp_commit();

    int wm = wid * 16;
    int lrow = lane & 15, lg = lane >> 4;

    float s[8][4], o[8][4], lacc[4];
#pragma unroll
    for (int i = 0; i < 8; i++)
#pragma unroll
        for (int j = 0; j < 4; j++) o[i][j] = 0.f;
#pragma unroll
    for (int j = 0; j < 4; j++) lacc[j] = 0.f;
    uint32_t qf[4][4];

    for (int st = 0; st < 8; st++) {
        cp_wait<0>();
        __syncthreads();
        if (st + 1 < 8) { stage_kv(st + 1); cp_commit(); }
        if (st == 0) {
#pragma unroll
            for (int kc = 0; kc < 4; kc++) {
                int row = wm + lrow;
                uint32_t off = (uint32_t)row*128 + (uint32_t)(((kc*2 + lg) ^ (row & 7)) << 4);
                ldx4(qf[kc], sb + off);
            }
        }
        uint32_t kb0 = sb + 16384u + (uint32_t)(st & 1)*AKV;

#pragma unroll
        for (int half = 0; half < 2; half++) {
            int r0 = half * 64;

            // ---- S = Q K^T (scores in log2 domain) ----
#pragma unroll
            for (int i = 0; i < 8; i++)
#pragma unroll
                for (int j = 0; j < 4; j++) s[i][j] = 0.f;
#pragma unroll
            for (int kc = 0; kc < 4; kc++) {
#pragma unroll
                for (int ng = 0; ng < 4; ng++) {
                    int row = r0 + ng*16 + lrow;
                    uint32_t off = (uint32_t)row*128 + (uint32_t)(((kc*2 + lg) ^ (row & 7)) << 4);
                    uint32_t kh4[4];
                    ldx4(kh4, kb0 + off);
                    mma16816h(s[2*ng+0], qf[kc], kh4[0], kh4[2]);
                    mma16816h(s[2*ng+1], qf[kc], kh4[1], kh4[3]);
                }
            }

            // ---- P = exp2(S) fused into f16x2 pack; O += P V; l += P @ 1 ----
#pragma unroll
            for (int kc = 0; kc < 4; kc++) {
                uint32_t pah[4];
                pah[0] = h2exp2(pack_h2(s[2*kc][0],   s[2*kc][1]));
                pah[1] = h2exp2(pack_h2(s[2*kc][2],   s[2*kc][3]));
                pah[2] = h2exp2(pack_h2(s[2*kc+1][0], s[2*kc+1][1]));
                pah[3] = h2exp2(pack_h2(s[2*kc+1][2], s[2*kc+1][3]));
                mma16816h(lacc, pah, ONE2, ONE2);
                int g = lane >> 3;
                int vrow = r0 + kc*16 + (g & 1)*8 + (lane & 7);
#pragma unroll
                for (int nf2 = 0; nf2 < 4; nf2++) {
                    int chv = nf2*2 + (g >> 1);
                    uint32_t va = kb0 + 16384u + (uint32_t)vrow*128
                                + (uint32_t)((chv ^ (vrow & 7)) << 4);
                    uint32_t vh4[4];
                    ldx4t(vh4, va);
                    mma16816h(o[2*nf2+0], pah, vh4[0], vh4[1]);
                    mma16816h(o[2*nf2+1], pah, vh4[2], vh4[3]);
                }
            }
        }
    }

    // lacc cols are all equal: lacc[0] = row sum (row r), lacc[2] = row r+8
    float ri0 = 1.f / lacc[0], ri1 = 1.f / lacc[2];
    int r = lane >> 2, c2 = (lane & 3) * 2;
#pragma unroll
    for (int nf = 0; nf < 8; nf++) {
        size_t i0 = (size_t)(b*TT + q0 + wm + r)*CC     + h*HD + nf*8 + c2;
        size_t i1 = (size_t)(b*TT + q0 + wm + r + 8)*CC + h*HD + nf*8 + c2;
        *(uint32_t*)(g_Yh + i0) = pack_h2(o[nf][0]*ri0, o[nf][1]*ri0);
        *(uint32_t*)(g_Yh + i1) = pack_h2(o[nf][2]*ri1, o[nf][3]*ri1);
    }
}

// ---------------------------------------------------------------------------
extern "C" void kernel_launch(void* const* d_in, const int* in_sizes, int n_in,
                              void* d_out, int out_size)
{
    const float* q       = (const float*)d_in[0];
    const float* kv      = (const float*)d_in[1];
    const float* ln_kv_w = (const float*)d_in[2];
    const float* ln_kv_b = (const float*)d_in[3];
    const float* ln_q_w  = (const float*)d_in[4];
    const float* ln_q_b  = (const float*)d_in[5];
    const float* Wk      = (const float*)d_in[6];
    const float* bk      = (const float*)d_in[7];
    const float* Wq      = (const float*)d_in[8];
    const float* bq      = (const float*)d_in[9];
    const float* Wv      = (const float*)d_in[10];
    const float* bv      = (const float*)d_in[11];
    const float* Wp      = (const float*)d_in[12];
    const float* bp      = (const float*)d_in[13];
    float* out = (float*)d_out;

    __half *kvh, *qh, *Yh, *Wt, *KO, *QO, *VO;
    cudaGetSymbolAddress((void**)&kvh, g_kvh);
    cudaGetSymbolAddress((void**)&qh,  g_qh);
    cudaGetSymbolAddress((void**)&Yh,  g_Yh);
    cudaGetSymbolAddress((void**)&Wt,  g_Wt);
    cudaGetSymbolAddress((void**)&KO,  g_KO);
    cudaGetSymbolAddress((void**)&QO,  g_QO);
    cudaGetSymbolAddress((void**)&VO,  g_VO);

    const int ASM_SZ = 16384 + 2*AKV;   // 81920 B
    cudaFuncSetAttribute(gemm_qkv, cudaFuncAttributeMaxDynamicSharedMemorySize, DSMG);
    cudaFuncSetAttribute(gemm_p,   cudaFuncAttributeMaxDynamicSharedMemorySize, DSMG);
    cudaFuncSetAttribute(attn_tc,  cudaFuncAttributeMaxDynamicSharedMemorySize, ASM_SZ);

    wprep_kernel<<<dim3(16,16,4), 256>>>(Wk, Wq, Wv, Wp, Wt);
    ln2_kernel<<<dim3(TT/8, BB, 2), 256>>>(kv, q, ln_kv_w, ln_kv_b,
                                           ln_q_w, ln_q_b, kvh, qh);

    gemm_qkv<<<dim3(CC/64, MM/128, 3), 256, DSMG>>>(
        kvh, qh, Wt, bk, bq, bv, KO, QO, VO);

    attn_tc<<<dim3(TT/128, NHD, BB), 256, ASM_SZ>>>();

    gemm_p<<<dim3(CC/64, MM/128), 256, DSMG>>>(Yh, Wt + 3*CC*CC, bp, kv, out);
}